// round 1
// baseline (speedup 1.0000x reference)
#include <cuda_runtime.h>

// Problem shape: [B=2, C=1, D=160, H=192, W=160], fp32, WIN=9 (radius 4), SAME zero pad.
#define Bn 2
#define Dn 160
#define Hn 192
#define Wn 160
#define NV (Bn*Dn*Hn*Wn)          // 9,830,400 voxels
#define RW 4                       // window radius
#define WSZ 729.0f                 // 9^3

// Scratch (static device globals — allocation inside kernel_launch is forbidden).
// Layout: channel-major, g_buf[c*NV + linear_voxel], c in {I, J, I2, J2, IJ}.
__device__ float g_bufA[5ll * NV];
__device__ float g_bufB[5ll * NV];
__device__ float g_part[240];      // per-block cc partial sums from dpass

// ---------------------------------------------------------------------------
// Pass 1: compute 5 products and window-sum along W (contiguous axis).
// One block per line (B*D*H = 61440 lines), 160 threads = one thread per w.
// ---------------------------------------------------------------------------
__global__ void ncc_wpass(const float* __restrict__ I, const float* __restrict__ J) {
    __shared__ float sp[5][Wn];
    const int L = blockIdx.x;          // line index over (b, d, h)
    const int t = threadIdx.x;         // w
    const size_t off = (size_t)L * Wn + t;

    const float a = I[off];
    const float b = J[off];
    sp[0][t] = a;
    sp[1][t] = b;
    sp[2][t] = a * a;
    sp[3][t] = b * b;
    sp[4][t] = a * b;
    __syncthreads();

    int lo = t - RW; if (lo < 0) lo = 0;
    int hi = t + RW; if (hi > Wn - 1) hi = Wn - 1;
    float s0 = 0.f, s1 = 0.f, s2 = 0.f, s3 = 0.f, s4 = 0.f;
    for (int k = lo; k <= hi; ++k) {
        s0 += sp[0][k];
        s1 += sp[1][k];
        s2 += sp[2][k];
        s3 += sp[3][k];
        s4 += sp[4][k];
    }
    g_bufA[0ll * NV + off] = s0;
    g_bufA[1ll * NV + off] = s1;
    g_bufA[2ll * NV + off] = s2;
    g_bufA[3ll * NV + off] = s3;
    g_bufA[4ll * NV + off] = s4;
}

// ---------------------------------------------------------------------------
// Pass 2: running sliding-window sum along H.
// One thread per (c, b, d, w) column: 5*2*160*160 = 256000 threads.
// Consecutive threads -> consecutive w -> coalesced loads/stores each h step.
// ---------------------------------------------------------------------------
__global__ void ncc_hpass() {
    const int tid = blockIdx.x * blockDim.x + threadIdx.x;   // < 256000
    const int w = tid % Wn;
    int r = tid / Wn;
    const int d = r % Dn; r /= Dn;
    const int b = r % Bn;
    const int c = r / Bn;

    const size_t base = (size_t)c * NV + (((size_t)b * Dn + d) * Hn) * Wn + w;
    const float* __restrict__ in = g_bufA;
    float* __restrict__ out = g_bufB;

    float s = 0.f;
    #pragma unroll
    for (int h = 0; h < RW; ++h) s += in[base + (size_t)h * Wn];

    for (int ho = 0; ho < Hn; ++ho) {
        if (ho + RW < Hn) s += in[base + (size_t)(ho + RW) * Wn];
        out[base + (size_t)ho * Wn] = s;
        if (ho - RW >= 0) s -= in[base + (size_t)(ho - RW) * Wn];
    }
}

// ---------------------------------------------------------------------------
// Pass 3: running sliding-window sum along D, fused with cc + block reduction.
// One thread per (b, h, w): 2*192*160 = 61440 threads = 240 blocks x 256.
// Deterministic: partials written to g_part, no atomics.
// ---------------------------------------------------------------------------
__global__ void ncc_dpass() {
    const int tid = blockIdx.x * blockDim.x + threadIdx.x;   // < 61440
    const int w = tid % Wn;
    int r = tid / Wn;
    const int h = r % Hn;
    const int b = r / Hn;

    const size_t dS = (size_t)Hn * Wn;
    const size_t base = ((size_t)b * Dn) * dS + (size_t)h * Wn + w;
    const float* __restrict__ in = g_bufB;

    float s0 = 0.f, s1 = 0.f, s2 = 0.f, s3 = 0.f, s4 = 0.f;
    #pragma unroll
    for (int d = 0; d < RW; ++d) {
        const size_t o = base + (size_t)d * dS;
        s0 += in[0ll * NV + o];
        s1 += in[1ll * NV + o];
        s2 += in[2ll * NV + o];
        s3 += in[3ll * NV + o];
        s4 += in[4ll * NV + o];
    }

    const float inv = 1.0f / WSZ;
    float acc = 0.f;
    for (int dout = 0; dout < Dn; ++dout) {
        if (dout + RW < Dn) {
            const size_t o = base + (size_t)(dout + RW) * dS;
            s0 += in[0ll * NV + o];
            s1 += in[1ll * NV + o];
            s2 += in[2ll * NV + o];
            s3 += in[3ll * NV + o];
            s4 += in[4ll * NV + o];
        }
        // cc = cross^2 / (I_var * J_var + 1e-5), all from window sums.
        const float uI = s0 * inv;
        const float uJ = s1 * inv;
        const float cross = s4 - uJ * s0 - uI * s1 + uI * uJ * WSZ;
        const float Iv = s2 - 2.0f * uI * s0 + uI * uI * WSZ;
        const float Jv = s3 - 2.0f * uJ * s1 + uJ * uJ * WSZ;
        acc += cross * cross / (Iv * Jv + 1e-5f);

        if (dout - RW >= 0) {
            const size_t o = base + (size_t)(dout - RW) * dS;
            s0 -= in[0ll * NV + o];
            s1 -= in[1ll * NV + o];
            s2 -= in[2ll * NV + o];
            s3 -= in[3ll * NV + o];
            s4 -= in[4ll * NV + o];
        }
    }

    __shared__ float red[256];
    red[threadIdx.x] = acc;
    __syncthreads();
    #pragma unroll
    for (int st = 128; st > 0; st >>= 1) {
        if (threadIdx.x < st) red[threadIdx.x] += red[threadIdx.x + st];
        __syncthreads();
    }
    if (threadIdx.x == 0) g_part[blockIdx.x] = red[0];
}

// ---------------------------------------------------------------------------
// Finalize: deterministic reduce of 240 partials in double, write scalar.
// ---------------------------------------------------------------------------
__global__ void ncc_finalize(float* __restrict__ out) {
    __shared__ double red[256];
    double v = 0.0;
    if (threadIdx.x < 240) v = (double)g_part[threadIdx.x];
    red[threadIdx.x] = v;
    __syncthreads();
    #pragma unroll
    for (int st = 128; st > 0; st >>= 1) {
        if (threadIdx.x < st) red[threadIdx.x] += red[threadIdx.x + st];
        __syncthreads();
    }
    if (threadIdx.x == 0) {
        out[0] = (float)(-(red[0] / (double)NV));
    }
}

extern "C" void kernel_launch(void* const* d_in, const int* in_sizes, int n_in,
                              void* d_out, int out_size) {
    const float* I = (const float*)d_in[0];   // y_true
    const float* J = (const float*)d_in[1];   // y_pred
    float* out = (float*)d_out;

    ncc_wpass<<<Bn * Dn * Hn, Wn>>>(I, J);                 // 61440 blocks x 160
    ncc_hpass<<<(5 * Bn * Dn * Wn) / 256, 256>>>();        // 1000 blocks x 256
    ncc_dpass<<<(Bn * Hn * Wn) / 256, 256>>>();            // 240 blocks x 256
    ncc_finalize<<<1, 256>>>(out);
}

// round 2
// speedup vs baseline: 1.4457x; 1.4457x over previous
#include <cuda_runtime.h>

// Shape: [B=2, C=1, D=160, H=192, W=160] fp32, WIN=9 (radius 4), SAME zero pad.
#define Bn 2
#define Dn 160
#define Hn 192
#define Wn 160
#define NV (Bn*Dn*Hn*Wn)            // 9,830,400
#define RW 4
#define WSZ 729.0f

// Fused pass tiling
#define TH 24                        // output rows per block (192 = 8*24)
#define ROWS (TH + 2*RW)             // 32 input rows (with halo)
#define RSTR 164                     // padded smem row stride (banks: 164%32=4)
#define SMEM_BYTES (5 * ROWS * RSTR * 4)   // 104,960 B

// D-pass split
#define NCOL (Bn*Hn*Wn)              // 61,440 columns
#define DSEG 2
#define DPB ((NCOL*DSEG)/256)        // 480 blocks

// Scratch: single intermediate buffer, channel-major [c][b][d][h][w].
__device__ float g_buf[5ll * NV];
__device__ float g_part[DPB];

#define P(ch, r, w) sm[((ch) * ROWS + (r)) * RSTR + (w)]

// ---------------------------------------------------------------------------
// Fused W+H pass: products -> W window-sum (in-place) -> H window-sum -> gmem.
// Block: 256 threads, tile = (b, d, h0..h0+TH) x full W.
// ---------------------------------------------------------------------------
__global__ void ncc_fused(const float* __restrict__ I, const float* __restrict__ J) {
    extern __shared__ float sm[];
    const int t = threadIdx.x;
    const int tile = blockIdx.x;
    const int ht = tile & 7;            // 8 tiles along H
    const int slice = tile >> 3;        // (b, d)
    const int d = slice % Dn;
    const int b = slice / Dn;
    const int h0 = ht * TH;

    // Phase A: load I,J rows [h0-4, h0+TH+4), compute 5 products into smem.
    for (int idx = t; idx < ROWS * Wn; idx += 256) {
        const int r = idx / Wn;
        const int w = idx - r * Wn;
        const int hg = h0 - RW + r;
        float a = 0.f, bb = 0.f;
        if (hg >= 0 && hg < Hn) {
            const size_t o = ((size_t)(b * Dn + d) * Hn + hg) * Wn + w;
            a = I[o];
            bb = J[o];
        }
        P(0, r, w) = a;
        P(1, r, w) = bb;
        P(2, r, w) = a * a;
        P(3, r, w) = bb * bb;
        P(4, r, w) = a * bb;
    }
    __syncthreads();

    // Phase B: W window-sum in-place, running sum per (row, 20-wide w chunk).
    // 32 rows x 8 chunks = 256 jobs = 1 per thread.
    {
        const int row = t >> 3;
        const int c0 = (t & 7) * 20;
        for (int ch = 0; ch < 5; ++ch) {
            float out[20];
            float s = 0.f;
            #pragma unroll
            for (int k = c0 - RW; k <= c0 + RW; ++k)
                if (k >= 0 && k < Wn) s += P(ch, row, k);
            #pragma unroll
            for (int i = 0; i < 20; ++i) {
                out[i] = s;
                const int w = c0 + i;
                if (w + RW + 1 < Wn) s += P(ch, row, w + RW + 1);
                if (w - RW >= 0)     s -= P(ch, row, w - RW);
            }
            __syncthreads();
            #pragma unroll
            for (int i = 0; i < 20; ++i) P(ch, row, c0 + i) = out[i];
            __syncthreads();
        }
    }

    // Phase C: H window-sum (rows o..o+8) per (ch, w) column, store to gmem.
    for (int job = t; job < 5 * Wn; job += 256) {
        const int w = job % Wn;          // w fastest -> coalesced stores
        const int ch = job / Wn;
        float s = 0.f;
        #pragma unroll
        for (int r = 0; r < 2 * RW; ++r) s += P(ch, r, w);
        const size_t obase = (size_t)ch * NV + ((size_t)(b * Dn + d) * Hn + h0) * Wn + w;
        #pragma unroll 4
        for (int o = 0; o < TH; ++o) {
            s += P(ch, o + 2 * RW, w);
            g_buf[obase + (size_t)o * Wn] = s;
            s -= P(ch, o, w);
        }
    }
}

// ---------------------------------------------------------------------------
// D-pass fused with cc + block reduction. D split into 2 segments per column.
// 480 blocks x 256 threads.
// ---------------------------------------------------------------------------
__global__ void ncc_dpass() {
    const int tid = blockIdx.x * blockDim.x + threadIdx.x;   // < 122880
    const int seg = tid / NCOL;
    const int col = tid - seg * NCOL;
    const int w = col % Wn;
    int r = col / Wn;
    const int h = r % Hn;
    const int b = r / Hn;
    const int d0 = seg * (Dn / DSEG);
    const int d1 = d0 + (Dn / DSEG);

    const size_t dS = (size_t)Hn * Wn;
    const size_t base = ((size_t)b * Dn) * dS + (size_t)h * Wn + w;
    const float* __restrict__ in = g_buf;

    float s0 = 0.f, s1 = 0.f, s2 = 0.f, s3 = 0.f, s4 = 0.f;
    #pragma unroll
    for (int d = d0 - RW; d < d0 + RW; ++d) {
        if (d >= 0 && d < Dn) {
            const size_t o = base + (size_t)d * dS;
            s0 += in[0ll * NV + o];
            s1 += in[1ll * NV + o];
            s2 += in[2ll * NV + o];
            s3 += in[3ll * NV + o];
            s4 += in[4ll * NV + o];
        }
    }

    const float inv = 1.0f / WSZ;
    float acc = 0.f;
    for (int dout = d0; dout < d1; ++dout) {
        if (dout + RW < Dn) {
            const size_t o = base + (size_t)(dout + RW) * dS;
            s0 += in[0ll * NV + o];
            s1 += in[1ll * NV + o];
            s2 += in[2ll * NV + o];
            s3 += in[3ll * NV + o];
            s4 += in[4ll * NV + o];
        }
        const float uI = s0 * inv;
        const float uJ = s1 * inv;
        const float cross = s4 - uJ * s0 - uI * s1 + uI * uJ * WSZ;
        const float Iv = s2 - 2.0f * uI * s0 + uI * uI * WSZ;
        const float Jv = s3 - 2.0f * uJ * s1 + uJ * uJ * WSZ;
        acc += cross * cross / (Iv * Jv + 1e-5f);
        if (dout - RW >= 0) {
            const size_t o = base + (size_t)(dout - RW) * dS;
            s0 -= in[0ll * NV + o];
            s1 -= in[1ll * NV + o];
            s2 -= in[2ll * NV + o];
            s3 -= in[3ll * NV + o];
            s4 -= in[4ll * NV + o];
        }
    }

    __shared__ float red[256];
    red[threadIdx.x] = acc;
    __syncthreads();
    #pragma unroll
    for (int st = 128; st > 0; st >>= 1) {
        if (threadIdx.x < st) red[threadIdx.x] += red[threadIdx.x + st];
        __syncthreads();
    }
    if (threadIdx.x == 0) g_part[blockIdx.x] = red[0];
}

// ---------------------------------------------------------------------------
// Finalize: deterministic reduce of 480 partials in double.
// ---------------------------------------------------------------------------
__global__ void ncc_finalize(float* __restrict__ out) {
    __shared__ double red[512];
    double v = 0.0;
    if (threadIdx.x < DPB) v = (double)g_part[threadIdx.x];
    red[threadIdx.x] = v;
    __syncthreads();
    #pragma unroll
    for (int st = 256; st > 0; st >>= 1) {
        if (threadIdx.x < st) red[threadIdx.x] += red[threadIdx.x + st];
        __syncthreads();
    }
    if (threadIdx.x == 0) {
        out[0] = (float)(-(red[0] / (double)NV));
    }
}

extern "C" void kernel_launch(void* const* d_in, const int* in_sizes, int n_in,
                              void* d_out, int out_size) {
    const float* I = (const float*)d_in[0];
    const float* J = (const float*)d_in[1];
    float* out = (float*)d_out;

    cudaFuncSetAttribute(ncc_fused, cudaFuncAttributeMaxDynamicSharedMemorySize,
                         SMEM_BYTES);

    ncc_fused<<<Bn * Dn * (Hn / TH), 256, SMEM_BYTES>>>(I, J);  // 2560 blocks
    ncc_dpass<<<DPB, 256>>>();                                   // 480 blocks
    ncc_finalize<<<1, 512>>>(out);
}

// round 3
// speedup vs baseline: 2.2308x; 1.5430x over previous
#include <cuda_runtime.h>

// Shape: [B=2, C=1, D=160, H=192, W=160] fp32, WIN=9 (radius 4), SAME zero pad.
#define Bn 2
#define Dn 160
#define Hn 192
#define Wn 160
#define NV (Bn*Dn*Hn*Wn)            // 9,830,400
#define RW 4
#define WSZ 729.0f

// Fused W+H pass tiling: small tile for occupancy (4 blocks/SM @ 52.8 KB smem).
#define TH 8                         // output rows per block (192 = 24*8)
#define ROWS (TH + 2*RW)             // 16 input rows (with halo)
#define RSTR 165                     // odd stride -> conflict-free Phase B
#define SMEM_BYTES (5 * ROWS * RSTR * 4)   // 52,800 B

// D-pass split
#define NCOL (Bn*Hn*Wn)              // 61,440 columns
#define DSEG 4
#define DSEGLEN (Dn/DSEG)            // 40
#define DPB ((NCOL*DSEG)/256)        // 960 blocks

// Scratch: intermediate buffer, channel-major [c][b][d][h][w].
__device__ float g_buf[5ll * NV];
__device__ float g_part[DPB];
__device__ unsigned g_cnt = 0;       // self-resetting via atomicInc wrap

#define P(ch, r, w) sm[((ch) * ROWS + (r)) * RSTR + (w)]

// ---------------------------------------------------------------------------
// Fused W+H pass: products -> W window-sum (in-place) -> H window-sum -> gmem.
// 256 threads/block, tile = (b, d, h0..h0+TH) x full W.  7680 blocks.
// ---------------------------------------------------------------------------
__global__ void ncc_fused(const float* __restrict__ I, const float* __restrict__ J) {
    extern __shared__ float sm[];
    const int t = threadIdx.x;
    const int tile = blockIdx.x;
    const int ht = tile % (Hn / TH);       // 24 tiles along H
    const int slice = tile / (Hn / TH);    // (b, d)
    const int d = slice % Dn;
    const int b = slice / Dn;
    const int h0 = ht * TH;

    // Phase A: load I,J rows [h0-4, h0+TH+4), compute 5 products into smem.
    #pragma unroll
    for (int idx = t; idx < ROWS * Wn; idx += 256) {
        const int r = idx / Wn;
        const int w = idx - r * Wn;
        const int hg = h0 - RW + r;
        float a = 0.f, bb = 0.f;
        if (hg >= 0 && hg < Hn) {
            const size_t o = ((size_t)(b * Dn + d) * Hn + hg) * Wn + w;
            a = I[o];
            bb = J[o];
        }
        P(0, r, w) = a;
        P(1, r, w) = bb;
        P(2, r, w) = a * a;
        P(3, r, w) = bb * bb;
        P(4, r, w) = a * bb;
    }
    __syncthreads();

    // Phase B: W window-sum in-place. 16 rows x 16 chunks of 10 = 256 jobs.
    {
        const int row = t >> 4;
        const int c0 = (t & 15) * 10;
        #pragma unroll
        for (int ch = 0; ch < 5; ++ch) {
            float out[10];
            float s = 0.f;
            #pragma unroll
            for (int k = c0 - RW; k <= c0 + RW; ++k)
                if (k >= 0 && k < Wn) s += P(ch, row, k);
            #pragma unroll
            for (int i = 0; i < 10; ++i) {
                out[i] = s;
                const int w = c0 + i;
                if (w + RW + 1 < Wn) s += P(ch, row, w + RW + 1);
                if (w - RW >= 0)     s -= P(ch, row, w - RW);
            }
            __syncthreads();
            #pragma unroll
            for (int i = 0; i < 10; ++i) P(ch, row, c0 + i) = out[i];
            __syncthreads();
        }
    }

    // Phase C: H window-sum (running over 16 rows -> 8 outputs), store to gmem.
    for (int job = t; job < 5 * Wn; job += 256) {
        const int w = job % Wn;          // w fastest -> coalesced stores
        const int ch = job / Wn;
        float s = 0.f;
        #pragma unroll
        for (int r = 0; r < 2 * RW; ++r) s += P(ch, r, w);
        const size_t obase = (size_t)ch * NV + ((size_t)(b * Dn + d) * Hn + h0) * Wn + w;
        #pragma unroll
        for (int o = 0; o < TH; ++o) {
            s += P(ch, o + 2 * RW, w);
            g_buf[obase + (size_t)o * Wn] = s;
            s -= P(ch, o, w);
        }
    }
}

// ---------------------------------------------------------------------------
// D-pass fused with cc + reduction + last-block finalize.
// 960 blocks x 256 threads, 4 D-segments of 40 per column.
// ---------------------------------------------------------------------------
__global__ void ncc_dpass(float* __restrict__ outp) {
    const int tid = blockIdx.x * blockDim.x + threadIdx.x;   // < 245760
    const int seg = tid / NCOL;
    const int col = tid - seg * NCOL;
    const int w = col % Wn;
    int r = col / Wn;
    const int h = r % Hn;
    const int b = r / Hn;
    const int d0 = seg * DSEGLEN;
    const int d1 = d0 + DSEGLEN;

    const size_t dS = (size_t)Hn * Wn;
    const size_t base = ((size_t)b * Dn) * dS + (size_t)h * Wn + w;
    const float* __restrict__ in = g_buf;

    float s0 = 0.f, s1 = 0.f, s2 = 0.f, s3 = 0.f, s4 = 0.f;
    #pragma unroll
    for (int d = d0 - RW; d < d0 + RW; ++d) {
        if (d >= 0 && d < Dn) {
            const size_t o = base + (size_t)d * dS;
            s0 += in[0ll * NV + o];
            s1 += in[1ll * NV + o];
            s2 += in[2ll * NV + o];
            s3 += in[3ll * NV + o];
            s4 += in[4ll * NV + o];
        }
    }

    const float inv = 1.0f / WSZ;
    float acc = 0.f;
    for (int dout = d0; dout < d1; ++dout) {
        if (dout + RW < Dn) {
            const size_t o = base + (size_t)(dout + RW) * dS;
            s0 += in[0ll * NV + o];
            s1 += in[1ll * NV + o];
            s2 += in[2ll * NV + o];
            s3 += in[3ll * NV + o];
            s4 += in[4ll * NV + o];
        }
        const float uI = s0 * inv;
        const float uJ = s1 * inv;
        const float cross = s4 - uJ * s0 - uI * s1 + uI * uJ * WSZ;
        const float Iv = s2 - 2.0f * uI * s0 + uI * uI * WSZ;
        const float Jv = s3 - 2.0f * uJ * s1 + uJ * uJ * WSZ;
        acc += cross * cross / (Iv * Jv + 1e-5f);
        if (dout - RW >= 0) {
            const size_t o = base + (size_t)(dout - RW) * dS;
            s0 -= in[0ll * NV + o];
            s1 -= in[1ll * NV + o];
            s2 -= in[2ll * NV + o];
            s3 -= in[3ll * NV + o];
            s4 -= in[4ll * NV + o];
        }
    }

    __shared__ float red[256];
    red[threadIdx.x] = acc;
    __syncthreads();
    #pragma unroll
    for (int st = 128; st > 0; st >>= 1) {
        if (threadIdx.x < st) red[threadIdx.x] += red[threadIdx.x + st];
        __syncthreads();
    }

    __shared__ bool is_last;
    if (threadIdx.x == 0) {
        g_part[blockIdx.x] = red[0];
        __threadfence();
        unsigned old = atomicInc(&g_cnt, DPB - 1);   // wraps to 0 -> replay-safe
        is_last = (old == DPB - 1);
    }
    __syncthreads();

    if (is_last) {
        // Deterministic fixed-order double sum of all partials.
        const volatile float* vp = g_part;
        double v = 0.0;
        for (int i = threadIdx.x; i < DPB; i += 256) v += (double)vp[i];
        __shared__ double dred[256];
        dred[threadIdx.x] = v;
        __syncthreads();
        #pragma unroll
        for (int st = 128; st > 0; st >>= 1) {
            if (threadIdx.x < st) dred[threadIdx.x] += dred[threadIdx.x + st];
            __syncthreads();
        }
        if (threadIdx.x == 0) outp[0] = (float)(-(dred[0] / (double)NV));
    }
}

extern "C" void kernel_launch(void* const* d_in, const int* in_sizes, int n_in,
                              void* d_out, int out_size) {
    const float* I = (const float*)d_in[0];
    const float* J = (const float*)d_in[1];
    float* out = (float*)d_out;

    cudaFuncSetAttribute(ncc_fused, cudaFuncAttributeMaxDynamicSharedMemorySize,
                         SMEM_BYTES);

    ncc_fused<<<Bn * Dn * (Hn / TH), 256, SMEM_BYTES>>>(I, J);  // 7680 blocks
    ncc_dpass<<<DPB, 256>>>(out);                                // 960 blocks
}

// round 4
// speedup vs baseline: 2.5340x; 1.1359x over previous
#include <cuda_runtime.h>
#include <cuda_fp16.h>

// Shape: [B=2, C=1, D=160, H=192, W=160] fp32, WIN=9 (radius 4), SAME zero pad.
#define Bn 2
#define Dn 160
#define Hn 192
#define Wn 160
#define NV (Bn*Dn*Hn*Wn)            // 9,830,400
#define RW 4
#define WSZ 729.0f

// Fused W+H pass tiling (4 blocks/SM @ 52.8 KB smem).
#define TH 8                         // output rows per block
#define ROWS (TH + 2*RW)             // 16 input rows with halo
#define RSTR 165                     // odd stride -> conflict-free
#define SMEM_BYTES (5 * ROWS * RSTR * 4)   // 52,800 B

// D-pass split: threads own 2 adjacent w-columns (half2), 8 D-segments.
#define NCOLH (Bn*Hn*(Wn/2))         // 30,720 column-pairs
#define DSEG 8
#define DSEGLEN (Dn/DSEG)            // 20
#define DPB ((NCOLH*DSEG)/256)       // 960 blocks

// Intermediate buffer in fp16, channel-major [c][b][d][h][w]. ~98.3 MB.
__device__ __half g_hbuf[5ll * NV];
__device__ float g_part[DPB];
__device__ unsigned g_cnt = 0;       // wraps -> graph-replay safe

#define P(ch, r, w) sm[((ch) * ROWS + (r)) * RSTR + (w)]

// ---------------------------------------------------------------------------
// Fused W+H pass: products -> W window-sum (in-place) -> H window-sum -> fp16.
// 256 threads/block, tile = (b, d, h0..h0+TH) x full W.  7680 blocks.
// ---------------------------------------------------------------------------
__global__ void ncc_fused(const float* __restrict__ I, const float* __restrict__ J) {
    extern __shared__ float sm[];
    const int t = threadIdx.x;
    const int tile = blockIdx.x;
    const int ht = tile % (Hn / TH);
    const int slice = tile / (Hn / TH);
    const int d = slice % Dn;
    const int b = slice / Dn;
    const int h0 = ht * TH;

    // Phase A: float4 loads of I,J rows [h0-4, h0+TH+4), 5 products into smem.
    for (int idx = t; idx < ROWS * (Wn / 4); idx += 256) {
        const int r = idx / (Wn / 4);
        const int wq = (idx - r * (Wn / 4)) * 4;
        const int hg = h0 - RW + r;
        float4 a = make_float4(0.f, 0.f, 0.f, 0.f);
        float4 c = a;
        if (hg >= 0 && hg < Hn) {
            const size_t o = ((size_t)(b * Dn + d) * Hn + hg) * Wn + wq;
            a = *(const float4*)(I + o);
            c = *(const float4*)(J + o);
        }
        const float av[4] = {a.x, a.y, a.z, a.w};
        const float cv[4] = {c.x, c.y, c.z, c.w};
        #pragma unroll
        for (int i = 0; i < 4; ++i) {
            P(0, r, wq + i) = av[i];
            P(1, r, wq + i) = cv[i];
            P(2, r, wq + i) = av[i] * av[i];
            P(3, r, wq + i) = cv[i] * cv[i];
            P(4, r, wq + i) = av[i] * cv[i];
        }
    }
    __syncthreads();

    // Phase B: W window-sum in-place. 16 rows x 16 chunks of 10 = 256 jobs.
    {
        const int row = t >> 4;
        const int c0 = (t & 15) * 10;
        #pragma unroll
        for (int ch = 0; ch < 5; ++ch) {
            float out[10];
            float s = 0.f;
            #pragma unroll
            for (int k = c0 - RW; k <= c0 + RW; ++k)
                if (k >= 0 && k < Wn) s += P(ch, row, k);
            #pragma unroll
            for (int i = 0; i < 10; ++i) {
                out[i] = s;
                const int w = c0 + i;
                if (w + RW + 1 < Wn) s += P(ch, row, w + RW + 1);
                if (w - RW >= 0)     s -= P(ch, row, w - RW);
            }
            __syncthreads();
            #pragma unroll
            for (int i = 0; i < 10; ++i) P(ch, row, c0 + i) = out[i];
            __syncthreads();
        }
    }

    // Phase C: H window-sum, 2 adjacent w per thread, half2 stores.
    // Jobs: 5 ch x 80 w-pairs = 400.
    for (int job = t; job < 5 * (Wn / 2); job += 256) {
        const int wp = job % (Wn / 2);
        const int ch = job / (Wn / 2);
        const int w0 = wp * 2;
        float sa = 0.f, sb = 0.f;
        #pragma unroll
        for (int r = 0; r < 2 * RW; ++r) {
            sa += P(ch, r, w0);
            sb += P(ch, r, w0 + 1);
        }
        const size_t obase = (size_t)ch * NV +
                             ((size_t)(b * Dn + d) * Hn + h0) * Wn + w0;
        __half2* __restrict__ ob = (__half2*)(g_hbuf + obase);
        #pragma unroll
        for (int o = 0; o < TH; ++o) {
            sa += P(ch, o + 2 * RW, w0);
            sb += P(ch, o + 2 * RW, w0 + 1);
            ob[(size_t)o * (Wn / 2)] = __halves2half2(__float2half_rn(sa),
                                                     __float2half_rn(sb));
            sa -= P(ch, o, w0);
            sb -= P(ch, o, w0 + 1);
        }
    }
}

// ---------------------------------------------------------------------------
// D-pass: running D window-sum (2 columns/thread) + cc + reduction + finalize.
// 960 blocks x 256 threads, 8 D-segments of 20 per column-pair.
// ---------------------------------------------------------------------------
__global__ void ncc_dpass(float* __restrict__ outp) {
    const int tid = blockIdx.x * blockDim.x + threadIdx.x;   // < 245760
    const int seg = tid / NCOLH;
    const int cp = tid - seg * NCOLH;
    const int wp = cp % (Wn / 2);
    int r = cp / (Wn / 2);
    const int h = r % Hn;
    const int b = r / Hn;
    const int d0 = seg * DSEGLEN;

    const size_t dS = (size_t)Hn * (Wn / 2);                 // half2 slice stride
    const size_t base = ((size_t)b * Dn) * dS + (size_t)h * (Wn / 2) + wp;
    const __half2* __restrict__ in = (const __half2*)g_hbuf;
    const size_t cNV = (size_t)NV / 2;                       // channel stride (half2)

    float2 s0 = {0.f, 0.f}, s1 = s0, s2 = s0, s3 = s0, s4 = s0;
    #pragma unroll
    for (int d = d0 - RW; d < d0 + RW; ++d) {
        if (d >= 0) {
            const size_t o = base + (size_t)d * dS;
            float2 v;
            v = __half22float2(in[0 * cNV + o]); s0.x += v.x; s0.y += v.y;
            v = __half22float2(in[1 * cNV + o]); s1.x += v.x; s1.y += v.y;
            v = __half22float2(in[2 * cNV + o]); s2.x += v.x; s2.y += v.y;
            v = __half22float2(in[3 * cNV + o]); s3.x += v.x; s3.y += v.y;
            v = __half22float2(in[4 * cNV + o]); s4.x += v.x; s4.y += v.y;
        }
    }

    const float inv = 1.0f / WSZ;
    float acc = 0.f;
    for (int dout = d0; dout < d0 + DSEGLEN; ++dout) {
        if (dout + RW < Dn) {
            const size_t o = base + (size_t)(dout + RW) * dS;
            float2 v;
            v = __half22float2(in[0 * cNV + o]); s0.x += v.x; s0.y += v.y;
            v = __half22float2(in[1 * cNV + o]); s1.x += v.x; s1.y += v.y;
            v = __half22float2(in[2 * cNV + o]); s2.x += v.x; s2.y += v.y;
            v = __half22float2(in[3 * cNV + o]); s3.x += v.x; s3.y += v.y;
            v = __half22float2(in[4 * cNV + o]); s4.x += v.x; s4.y += v.y;
        }
        {
            const float uI = s0.x * inv, uJ = s1.x * inv;
            const float cross = s4.x - uJ * s0.x - uI * s1.x + uI * uJ * WSZ;
            const float Iv = s2.x - 2.f * uI * s0.x + uI * uI * WSZ;
            const float Jv = s3.x - 2.f * uJ * s1.x + uJ * uJ * WSZ;
            acc += cross * cross / (Iv * Jv + 1e-5f);
        }
        {
            const float uI = s0.y * inv, uJ = s1.y * inv;
            const float cross = s4.y - uJ * s0.y - uI * s1.y + uI * uJ * WSZ;
            const float Iv = s2.y - 2.f * uI * s0.y + uI * uI * WSZ;
            const float Jv = s3.y - 2.f * uJ * s1.y + uJ * uJ * WSZ;
            acc += cross * cross / (Iv * Jv + 1e-5f);
        }
        if (dout - RW >= 0) {
            const size_t o = base + (size_t)(dout - RW) * dS;
            float2 v;
            v = __half22float2(in[0 * cNV + o]); s0.x -= v.x; s0.y -= v.y;
            v = __half22float2(in[1 * cNV + o]); s1.x -= v.x; s1.y -= v.y;
            v = __half22float2(in[2 * cNV + o]); s2.x -= v.x; s2.y -= v.y;
            v = __half22float2(in[3 * cNV + o]); s3.x -= v.x; s3.y -= v.y;
            v = __half22float2(in[4 * cNV + o]); s4.x -= v.x; s4.y -= v.y;
        }
    }

    __shared__ float red[256];
    red[threadIdx.x] = acc;
    __syncthreads();
    #pragma unroll
    for (int st = 128; st > 0; st >>= 1) {
        if (threadIdx.x < st) red[threadIdx.x] += red[threadIdx.x + st];
        __syncthreads();
    }

    __shared__ bool is_last;
    if (threadIdx.x == 0) {
        g_part[blockIdx.x] = red[0];
        __threadfence();
        unsigned old = atomicInc(&g_cnt, DPB - 1);
        is_last = (old == DPB - 1);
    }
    __syncthreads();

    if (is_last) {
        const volatile float* vp = g_part;
        double v = 0.0;
        for (int i = threadIdx.x; i < DPB; i += 256) v += (double)vp[i];
        __shared__ double dred[256];
        dred[threadIdx.x] = v;
        __syncthreads();
        #pragma unroll
        for (int st = 128; st > 0; st >>= 1) {
            if (threadIdx.x < st) dred[threadIdx.x] += dred[threadIdx.x + st];
            __syncthreads();
        }
        if (threadIdx.x == 0) outp[0] = (float)(-(dred[0] / (double)NV));
    }
}

extern "C" void kernel_launch(void* const* d_in, const int* in_sizes, int n_in,
                              void* d_out, int out_size) {
    const float* I = (const float*)d_in[0];
    const float* J = (const float*)d_in[1];
    float* out = (float*)d_out;

    cudaFuncSetAttribute(ncc_fused, cudaFuncAttributeMaxDynamicSharedMemorySize,
                         SMEM_BYTES);

    ncc_fused<<<Bn * Dn * (Hn / TH), 256, SMEM_BYTES>>>(I, J);  // 7680 blocks
    ncc_dpass<<<DPB, 256>>>(out);                                // 960 blocks
}

// round 5
// speedup vs baseline: 2.5358x; 1.0007x over previous
#include <cuda_runtime.h>
#include <cuda_fp16.h>

// Shape: [B=2, C=1, D=160, H=192, W=160] fp32, WIN=9 (radius 4), SAME zero pad.
#define Bn 2
#define Dn 160
#define Hn 192
#define Wn 160
#define NV (Bn*Dn*Hn*Wn)            // 9,830,400
#define RW 4
#define WSZ 729.0f

// Fused W+H pass tiling (4 blocks/SM @ 52.8 KB smem).
#define TH 8                         // output rows per block
#define ROWS (TH + 2*RW)             // 16 input rows with halo
#define RSTR 165                     // odd stride -> conflict-free
#define SMEM_BYTES (5 * ROWS * RSTR * 4)   // 52,800 B

// D-pass split: threads own 2 adjacent w-columns (half2), 8 D-segments.
#define NCOLH (Bn*Hn*(Wn/2))         // 30,720 column-pairs
#define DSEG 8
#define DSEGLEN (Dn/DSEG)            // 20
#define DPB ((NCOLH*DSEG)/256)       // 960 blocks

// Intermediate buffer in fp16, channel-major [c][b][d][h][w]. ~98.3 MB.
__device__ __half g_hbuf[5ll * NV];
__device__ float g_part[DPB];
__device__ unsigned g_cnt = 0;       // wraps -> graph-replay safe

#define P(ch, r, w) sm[((ch) * ROWS + (r)) * RSTR + (w)]

// ---------------------------------------------------------------------------
// Fused W+H pass: products -> W window-sum (in-place) -> H window-sum -> fp16.
// 256 threads/block, tile = (b, d, h0..h0+TH) x full W.  7680 blocks.
// ---------------------------------------------------------------------------
__global__ void ncc_fused(const float* __restrict__ I, const float* __restrict__ J) {
    extern __shared__ float sm[];
    const int t = threadIdx.x;
    const int tile = blockIdx.x;
    const int ht = tile % (Hn / TH);
    const int slice = tile / (Hn / TH);
    const int d = slice % Dn;
    const int b = slice / Dn;
    const int h0 = ht * TH;

    // Phase A: float4 loads of I,J rows [h0-4, h0+TH+4), 5 products into smem.
    for (int idx = t; idx < ROWS * (Wn / 4); idx += 256) {
        const int r = idx / (Wn / 4);
        const int wq = (idx - r * (Wn / 4)) * 4;
        const int hg = h0 - RW + r;
        float4 a = make_float4(0.f, 0.f, 0.f, 0.f);
        float4 c = a;
        if (hg >= 0 && hg < Hn) {
            const size_t o = ((size_t)(b * Dn + d) * Hn + hg) * Wn + wq;
            a = *(const float4*)(I + o);
            c = *(const float4*)(J + o);
        }
        const float av[4] = {a.x, a.y, a.z, a.w};
        const float cv[4] = {c.x, c.y, c.z, c.w};
        #pragma unroll
        for (int i = 0; i < 4; ++i) {
            P(0, r, wq + i) = av[i];
            P(1, r, wq + i) = cv[i];
            P(2, r, wq + i) = av[i] * av[i];
            P(3, r, wq + i) = cv[i] * cv[i];
            P(4, r, wq + i) = av[i] * cv[i];
        }
    }
    __syncthreads();

    // Phase B: W window-sum in-place. 16 rows x 16 chunks of 10 = 256 jobs.
    {
        const int row = t >> 4;
        const int c0 = (t & 15) * 10;
        #pragma unroll
        for (int ch = 0; ch < 5; ++ch) {
            float out[10];
            float s = 0.f;
            #pragma unroll
            for (int k = c0 - RW; k <= c0 + RW; ++k)
                if (k >= 0 && k < Wn) s += P(ch, row, k);
            #pragma unroll
            for (int i = 0; i < 10; ++i) {
                out[i] = s;
                const int w = c0 + i;
                if (w + RW + 1 < Wn) s += P(ch, row, w + RW + 1);
                if (w - RW >= 0)     s -= P(ch, row, w - RW);
            }
            __syncthreads();
            #pragma unroll
            for (int i = 0; i < 10; ++i) P(ch, row, c0 + i) = out[i];
            __syncthreads();
        }
    }

    // Phase C: H window-sum, 2 adjacent w per thread, half2 stores.
    // Jobs: 5 ch x 80 w-pairs = 400.
    for (int job = t; job < 5 * (Wn / 2); job += 256) {
        const int wp = job % (Wn / 2);
        const int ch = job / (Wn / 2);
        const int w0 = wp * 2;
        float sa = 0.f, sb = 0.f;
        #pragma unroll
        for (int r = 0; r < 2 * RW; ++r) {
            sa += P(ch, r, w0);
            sb += P(ch, r, w0 + 1);
        }
        const size_t obase = (size_t)ch * NV +
                             ((size_t)(b * Dn + d) * Hn + h0) * Wn + w0;
        __half2* __restrict__ ob = (__half2*)(g_hbuf + obase);
        #pragma unroll
        for (int o = 0; o < TH; ++o) {
            sa += P(ch, o + 2 * RW, w0);
            sb += P(ch, o + 2 * RW, w0 + 1);
            ob[(size_t)o * (Wn / 2)] = __halves2half2(__float2half_rn(sa),
                                                     __float2half_rn(sb));
            sa -= P(ch, o, w0);
            sb -= P(ch, o, w0 + 1);
        }
    }
}

// ---------------------------------------------------------------------------
// D-pass: running D window-sum (2 columns/thread) + cc + reduction + finalize.
// 960 blocks x 256 threads, 8 D-segments of 20 per column-pair.
// ---------------------------------------------------------------------------
__global__ void ncc_dpass(float* __restrict__ outp) {
    const int tid = blockIdx.x * blockDim.x + threadIdx.x;   // < 245760
    const int seg = tid / NCOLH;
    const int cp = tid - seg * NCOLH;
    const int wp = cp % (Wn / 2);
    int r = cp / (Wn / 2);
    const int h = r % Hn;
    const int b = r / Hn;
    const int d0 = seg * DSEGLEN;

    const size_t dS = (size_t)Hn * (Wn / 2);                 // half2 slice stride
    const size_t base = ((size_t)b * Dn) * dS + (size_t)h * (Wn / 2) + wp;
    const __half2* __restrict__ in = (const __half2*)g_hbuf;
    const size_t cNV = (size_t)NV / 2;                       // channel stride (half2)

    float2 s0 = {0.f, 0.f}, s1 = s0, s2 = s0, s3 = s0, s4 = s0;
    #pragma unroll
    for (int d = d0 - RW; d < d0 + RW; ++d) {
        if (d >= 0) {
            const size_t o = base + (size_t)d * dS;
            float2 v;
            v = __half22float2(in[0 * cNV + o]); s0.x += v.x; s0.y += v.y;
            v = __half22float2(in[1 * cNV + o]); s1.x += v.x; s1.y += v.y;
            v = __half22float2(in[2 * cNV + o]); s2.x += v.x; s2.y += v.y;
            v = __half22float2(in[3 * cNV + o]); s3.x += v.x; s3.y += v.y;
            v = __half22float2(in[4 * cNV + o]); s4.x += v.x; s4.y += v.y;
        }
    }

    const float inv = 1.0f / WSZ;
    float acc = 0.f;
    for (int dout = d0; dout < d0 + DSEGLEN; ++dout) {
        if (dout + RW < Dn) {
            const size_t o = base + (size_t)(dout + RW) * dS;
            float2 v;
            v = __half22float2(in[0 * cNV + o]); s0.x += v.x; s0.y += v.y;
            v = __half22float2(in[1 * cNV + o]); s1.x += v.x; s1.y += v.y;
            v = __half22float2(in[2 * cNV + o]); s2.x += v.x; s2.y += v.y;
            v = __half22float2(in[3 * cNV + o]); s3.x += v.x; s3.y += v.y;
            v = __half22float2(in[4 * cNV + o]); s4.x += v.x; s4.y += v.y;
        }
        {
            const float uI = s0.x * inv, uJ = s1.x * inv;
            const float cross = s4.x - uJ * s0.x - uI * s1.x + uI * uJ * WSZ;
            const float Iv = s2.x - 2.f * uI * s0.x + uI * uI * WSZ;
            const float Jv = s3.x - 2.f * uJ * s1.x + uJ * uJ * WSZ;
            acc += cross * cross / (Iv * Jv + 1e-5f);
        }
        {
            const float uI = s0.y * inv, uJ = s1.y * inv;
            const float cross = s4.y - uJ * s0.y - uI * s1.y + uI * uJ * WSZ;
            const float Iv = s2.y - 2.f * uI * s0.y + uI * uI * WSZ;
            const float Jv = s3.y - 2.f * uJ * s1.y + uJ * uJ * WSZ;
            acc += cross * cross / (Iv * Jv + 1e-5f);
        }
        if (dout - RW >= 0) {
            const size_t o = base + (size_t)(dout - RW) * dS;
            float2 v;
            v = __half22float2(in[0 * cNV + o]); s0.x -= v.x; s0.y -= v.y;
            v = __half22float2(in[1 * cNV + o]); s1.x -= v.x; s1.y -= v.y;
            v = __half22float2(in[2 * cNV + o]); s2.x -= v.x; s2.y -= v.y;
            v = __half22float2(in[3 * cNV + o]); s3.x -= v.x; s3.y -= v.y;
            v = __half22float2(in[4 * cNV + o]); s4.x -= v.x; s4.y -= v.y;
        }
    }

    __shared__ float red[256];
    red[threadIdx.x] = acc;
    __syncthreads();
    #pragma unroll
    for (int st = 128; st > 0; st >>= 1) {
        if (threadIdx.x < st) red[threadIdx.x] += red[threadIdx.x + st];
        __syncthreads();
    }

    __shared__ bool is_last;
    if (threadIdx.x == 0) {
        g_part[blockIdx.x] = red[0];
        __threadfence();
        unsigned old = atomicInc(&g_cnt, DPB - 1);
        is_last = (old == DPB - 1);
    }
    __syncthreads();

    if (is_last) {
        const volatile float* vp = g_part;
        double v = 0.0;
        for (int i = threadIdx.x; i < DPB; i += 256) v += (double)vp[i];
        __shared__ double dred[256];
        dred[threadIdx.x] = v;
        __syncthreads();
        #pragma unroll
        for (int st = 128; st > 0; st >>= 1) {
            if (threadIdx.x < st) dred[threadIdx.x] += dred[threadIdx.x + st];
            __syncthreads();
        }
        if (threadIdx.x == 0) outp[0] = (float)(-(dred[0] / (double)NV));
    }
}

extern "C" void kernel_launch(void* const* d_in, const int* in_sizes, int n_in,
                              void* d_out, int out_size) {
    const float* I = (const float*)d_in[0];
    const float* J = (const float*)d_in[1];
    float* out = (float*)d_out;

    cudaFuncSetAttribute(ncc_fused, cudaFuncAttributeMaxDynamicSharedMemorySize,
                         SMEM_BYTES);

    ncc_fused<<<Bn * Dn * (Hn / TH), 256, SMEM_BYTES>>>(I, J);  // 7680 blocks
    ncc_dpass<<<DPB, 256>>>(out);                                // 960 blocks
}

// round 6
// speedup vs baseline: 2.7110x; 1.0691x over previous
#include <cuda_runtime.h>
#include <cuda_fp16.h>

// Shape: [B=2, C=1, D=160, H=192, W=160] fp32, WIN=9 (radius 4), SAME zero pad.
#define Bn 2
#define Dn 160
#define Hn 192
#define Wn 160
#define NV (Bn*Dn*Hn*Wn)            // 9,830,400
#define RW 4
#define WSZ 729.0f

// Fused W+H pass tiling (3 blocks/SM @ 73.8 KB smem, 2 syncs total).
#define TH 8                         // output rows per block
#define ROWS (TH + 2*RW)             // 16 input rows with halo
#define ISTR 164                     // I/J smem stride (float4-aligned)
#define SSTR 165                     // W-sum smem stride (odd)
#define SM_IJ (ROWS * ISTR)          // one input plane
#define SM_S  (ROWS * SSTR)          // one W-sum plane
#define SMEM_BYTES ((2 * SM_IJ + 5 * SM_S) * 4)   // 73,792 B

// D-pass: 4 columns/thread (uint2 of half2), 16 D-segments.
#define NCOLQ (Bn*Hn*(Wn/4))         // 15,360 column-quads
#define DSEG 16
#define DSEGLEN (Dn/DSEG)            // 10
#define DPB ((NCOLQ*DSEG)/256)       // 960 blocks

// Intermediate buffer in fp16, channel-major [c][b][d][h][w]. ~98.3 MB.
__device__ __align__(16) __half g_hbuf[5ll * NV];
__device__ float g_part[DPB];
__device__ unsigned g_cnt = 0;       // wraps -> graph-replay safe

// ---------------------------------------------------------------------------
// Fused W+H pass: stage I,J -> W window-sums (products on the fly) -> H
// window-sum -> fp16 gmem.  256 threads/block, 7680 blocks.
// ---------------------------------------------------------------------------
__global__ void ncc_fused(const float* __restrict__ I, const float* __restrict__ J) {
    extern __shared__ float sm[];
    float* __restrict__ sI = sm;                   // [ROWS][ISTR]
    float* __restrict__ sJ = sm + SM_IJ;           // [ROWS][ISTR]
    float* __restrict__ sS = sm + 2 * SM_IJ;       // [5][ROWS][SSTR]

    const int t = threadIdx.x;
    const int tile = blockIdx.x;
    const int ht = tile % (Hn / TH);
    const int slice = tile / (Hn / TH);
    const int d = slice % Dn;
    const int b = slice / Dn;
    const int h0 = ht * TH;

    // Phase A: float4 loads of I,J rows [h0-4, h0+TH+4) into smem.
    for (int idx = t; idx < ROWS * (Wn / 4); idx += 256) {
        const int r = idx / (Wn / 4);
        const int wq = (idx - r * (Wn / 4)) * 4;
        const int hg = h0 - RW + r;
        float4 a = make_float4(0.f, 0.f, 0.f, 0.f);
        float4 c = a;
        if (hg >= 0 && hg < Hn) {
            const size_t o = ((size_t)(b * Dn + d) * Hn + hg) * Wn + wq;
            a = *(const float4*)(I + o);
            c = *(const float4*)(J + o);
        }
        *(float4*)(sI + r * ISTR + wq) = a;
        *(float4*)(sJ + r * ISTR + wq) = c;
    }
    __syncthreads();

    // Phase B: W window-sums for all 5 channels, products computed on the fly.
    // 16 rows x 16 chunks of 10 = 256 jobs; writes to separate region -> no
    // intermediate syncs.
    {
        const int row = t >> 4;
        const int c0 = (t & 15) * 10;
        const float* __restrict__ rI = sI + row * ISTR;
        const float* __restrict__ rJ = sJ + row * ISTR;
        float s0 = 0.f, s1 = 0.f, s2 = 0.f, s3 = 0.f, s4 = 0.f;
        #pragma unroll
        for (int k = c0 - RW; k <= c0 + RW; ++k) {
            if (k >= 0 && k < Wn) {
                const float a = rI[k], c = rJ[k];
                s0 += a; s1 += c; s2 += a * a; s3 += c * c; s4 += a * c;
            }
        }
        #pragma unroll
        for (int i = 0; i < 10; ++i) {
            const int w = c0 + i;
            sS[0 * SM_S + row * SSTR + w] = s0;
            sS[1 * SM_S + row * SSTR + w] = s1;
            sS[2 * SM_S + row * SSTR + w] = s2;
            sS[3 * SM_S + row * SSTR + w] = s3;
            sS[4 * SM_S + row * SSTR + w] = s4;
            if (w + RW + 1 < Wn) {
                const float a = rI[w + RW + 1], c = rJ[w + RW + 1];
                s0 += a; s1 += c; s2 += a * a; s3 += c * c; s4 += a * c;
            }
            if (w - RW >= 0) {
                const float a = rI[w - RW], c = rJ[w - RW];
                s0 -= a; s1 -= c; s2 -= a * a; s3 -= c * c; s4 -= a * c;
            }
        }
    }
    __syncthreads();

    // Phase C: H window-sum per (ch, w) column, fp16 stores.
    // 5*160 = 800 jobs; consecutive threads -> consecutive w (conflict-free
    // LDS, coalesced 2B stores).
    for (int job = t; job < 5 * Wn; job += 256) {
        const int w = job % Wn;
        const int ch = job / Wn;
        const float* __restrict__ col = sS + ch * SM_S + w;
        float s = 0.f;
        #pragma unroll
        for (int r = 0; r < 2 * RW; ++r) s += col[r * SSTR];
        __half* __restrict__ ob = g_hbuf + (size_t)ch * NV +
                                  ((size_t)(b * Dn + d) * Hn + h0) * Wn + w;
        #pragma unroll
        for (int o = 0; o < TH; ++o) {
            s += col[(o + 2 * RW) * SSTR];
            ob[(size_t)o * Wn] = __float2half_rn(s);
            s -= col[o * SSTR];
        }
    }
}

// ---------------------------------------------------------------------------
// D-pass: running D window-sum (4 columns/thread via LDG.64) + cc + reduction
// + last-block finalize.  960 blocks x 256 threads, 16 segments of 10.
// ---------------------------------------------------------------------------
__device__ __forceinline__ float4 cvt4(uint2 v) {
    const __half2 a = *reinterpret_cast<__half2*>(&v.x);
    const __half2 b = *reinterpret_cast<__half2*>(&v.y);
    const float2 fa = __half22float2(a);
    const float2 fb = __half22float2(b);
    return make_float4(fa.x, fa.y, fb.x, fb.y);
}

__global__ void ncc_dpass(float* __restrict__ outp) {
    const int tid = blockIdx.x * blockDim.x + threadIdx.x;   // < 245760
    const int seg = tid / NCOLQ;
    const int cp = tid - seg * NCOLQ;
    const int wq = cp % (Wn / 4);
    int r = cp / (Wn / 4);
    const int h = r % Hn;
    const int b = r / Hn;
    const int d0 = seg * DSEGLEN;

    const size_t dS = (size_t)Hn * (Wn / 4);                 // slice stride (uint2)
    const size_t base = ((size_t)b * Dn) * dS + (size_t)h * (Wn / 4) + wq;
    const uint2* __restrict__ in = (const uint2*)g_hbuf;
    const size_t cNV = (size_t)NV / 4;                       // channel stride (uint2)

    float4 s0 = {0.f, 0.f, 0.f, 0.f}, s1 = s0, s2 = s0, s3 = s0, s4 = s0;

    #pragma unroll
    for (int d = d0 - RW; d < d0 + RW; ++d) {
        if (d >= 0) {
            const size_t o = base + (size_t)d * dS;
            float4 v;
            v = cvt4(in[0 * cNV + o]); s0.x += v.x; s0.y += v.y; s0.z += v.z; s0.w += v.w;
            v = cvt4(in[1 * cNV + o]); s1.x += v.x; s1.y += v.y; s1.z += v.z; s1.w += v.w;
            v = cvt4(in[2 * cNV + o]); s2.x += v.x; s2.y += v.y; s2.z += v.z; s2.w += v.w;
            v = cvt4(in[3 * cNV + o]); s3.x += v.x; s3.y += v.y; s3.z += v.z; s3.w += v.w;
            v = cvt4(in[4 * cNV + o]); s4.x += v.x; s4.y += v.y; s4.z += v.z; s4.w += v.w;
        }
    }

    const float inv = 1.0f / WSZ;
    float acc = 0.f;
    #pragma unroll 2
    for (int dout = d0; dout < d0 + DSEGLEN; ++dout) {
        if (dout + RW < Dn) {
            const size_t o = base + (size_t)(dout + RW) * dS;
            float4 v;
            v = cvt4(in[0 * cNV + o]); s0.x += v.x; s0.y += v.y; s0.z += v.z; s0.w += v.w;
            v = cvt4(in[1 * cNV + o]); s1.x += v.x; s1.y += v.y; s1.z += v.z; s1.w += v.w;
            v = cvt4(in[2 * cNV + o]); s2.x += v.x; s2.y += v.y; s2.z += v.z; s2.w += v.w;
            v = cvt4(in[3 * cNV + o]); s3.x += v.x; s3.y += v.y; s3.z += v.z; s3.w += v.w;
            v = cvt4(in[4 * cNV + o]); s4.x += v.x; s4.y += v.y; s4.z += v.z; s4.w += v.w;
        }
        {
            const float* p0 = &s0.x; const float* p1 = &s1.x; const float* p2 = &s2.x;
            const float* p3 = &s3.x; const float* p4 = &s4.x;
            #pragma unroll
            for (int l = 0; l < 4; ++l) {
                const float uI = p0[l] * inv, uJ = p1[l] * inv;
                const float cross = p4[l] - uJ * p0[l] - uI * p1[l] + uI * uJ * WSZ;
                const float Iv = p2[l] - 2.f * uI * p0[l] + uI * uI * WSZ;
                const float Jv = p3[l] - 2.f * uJ * p1[l] + uJ * uJ * WSZ;
                acc += cross * cross / (Iv * Jv + 1e-5f);
            }
        }
        if (dout - RW >= 0) {
            const size_t o = base + (size_t)(dout - RW) * dS;
            float4 v;
            v = cvt4(in[0 * cNV + o]); s0.x -= v.x; s0.y -= v.y; s0.z -= v.z; s0.w -= v.w;
            v = cvt4(in[1 * cNV + o]); s1.x -= v.x; s1.y -= v.y; s1.z -= v.z; s1.w -= v.w;
            v = cvt4(in[2 * cNV + o]); s2.x -= v.x; s2.y -= v.y; s2.z -= v.z; s2.w -= v.w;
            v = cvt4(in[3 * cNV + o]); s3.x -= v.x; s3.y -= v.y; s3.z -= v.z; s3.w -= v.w;
            v = cvt4(in[4 * cNV + o]); s4.x -= v.x; s4.y -= v.y; s4.z -= v.z; s4.w -= v.w;
        }
    }

    __shared__ float red[256];
    red[threadIdx.x] = acc;
    __syncthreads();
    #pragma unroll
    for (int st = 128; st > 0; st >>= 1) {
        if (threadIdx.x < st) red[threadIdx.x] += red[threadIdx.x + st];
        __syncthreads();
    }

    __shared__ bool is_last;
    if (threadIdx.x == 0) {
        g_part[blockIdx.x] = red[0];
        __threadfence();
        unsigned old = atomicInc(&g_cnt, DPB - 1);
        is_last = (old == DPB - 1);
    }
    __syncthreads();

    if (is_last) {
        const volatile float* vp = g_part;
        double v = 0.0;
        for (int i = threadIdx.x; i < DPB; i += 256) v += (double)vp[i];
        __shared__ double dred[256];
        dred[threadIdx.x] = v;
        __syncthreads();
        #pragma unroll
        for (int st = 128; st > 0; st >>= 1) {
            if (threadIdx.x < st) dred[threadIdx.x] += dred[threadIdx.x + st];
            __syncthreads();
        }
        if (threadIdx.x == 0) outp[0] = (float)(-(dred[0] / (double)NV));
    }
}

extern "C" void kernel_launch(void* const* d_in, const int* in_sizes, int n_in,
                              void* d_out, int out_size) {
    const float* I = (const float*)d_in[0];
    const float* J = (const float*)d_in[1];
    float* out = (float*)d_out;

    cudaFuncSetAttribute(ncc_fused, cudaFuncAttributeMaxDynamicSharedMemorySize,
                         SMEM_BYTES);

    ncc_fused<<<Bn * Dn * (Hn / TH), 256, SMEM_BYTES>>>(I, J);  // 7680 blocks
    ncc_dpass<<<DPB, 256>>>(out);                                // 960 blocks
}